// round 9
// baseline (speedup 1.0000x reference)
#include <cuda_runtime.h>
#include <cuda_fp16.h>
#include <cstdint>

// Problem constants (local_emb_D: N_NODES=100000, N_HIDDEN=128, N_EDGES=625000)
#define H 128
#define MAX_NODES 100000

// Single fp16 gather table (25.6 MB, fully L2-resident):
//   g[n][h] = normalize(emb)[n][h] * sqrt(d[h]*scale)
// so that dot(g[src], g[dst]) = sum_h e_src*d*scale*e_dst (w>=0; here d=ones,
// scale=ones so sqrt(w)=1 and the split is exact).
__device__ __half g_eh[(size_t)MAX_NODES * H];

// ---------------------------------------------------------------------------
// Pass 1: L2-normalize each row, fold sqrt(d*scale), store fp16.
// One warp per row; lane i handles elements 4i..4i+3. HBM-floor bound.
// ---------------------------------------------------------------------------
__global__ void normalize_rows(const float* __restrict__ emb,
                               const float* __restrict__ d,
                               const float* __restrict__ scale,
                               int n_nodes) {
    int warp = (blockIdx.x * blockDim.x + threadIdx.x) >> 5;
    int lane = threadIdx.x & 31;
    if (warp >= n_nodes) return;

    const float4* row = reinterpret_cast<const float4*>(emb) + (size_t)warp * (H / 4);
    float4 v = row[lane];

    float s = v.x * v.x + v.y * v.y + v.z * v.z + v.w * v.w;
#pragma unroll
    for (int o = 16; o > 0; o >>= 1) s += __shfl_xor_sync(0xffffffffu, s, o);

    float inv = 1.0f / fmaxf(sqrtf(s), 1e-12f);

    float4 dv = reinterpret_cast<const float4*>(d)[lane];
    float sc = scale[0];
    float wx = sqrtf(dv.x * sc), wy = sqrtf(dv.y * sc);
    float wz = sqrtf(dv.z * sc), ww = sqrtf(dv.w * sc);

    __half2 h0 = __floats2half2_rn(v.x * inv * wx, v.y * inv * wy);
    __half2 h1 = __floats2half2_rn(v.z * inv * wz, v.w * inv * ww);
    uint2 p;
    p.x = *reinterpret_cast<unsigned int*>(&h0);
    p.y = *reinterpret_cast<unsigned int*>(&h1);
    reinterpret_cast<uint2*>(g_eh)[(size_t)warp * (H / 4) + lane] = p;
}

// ---------------------------------------------------------------------------
// Lane-local dot of 16 fp16 pairs via HFMA2 (8 fused ops), then one cvt.
// ---------------------------------------------------------------------------
__device__ __forceinline__ float dot16h(uint4 a0, uint4 a1, uint4 b0, uint4 b1) {
    const __half2* ha0 = reinterpret_cast<const __half2*>(&a0.x);
    const __half2* hb0 = reinterpret_cast<const __half2*>(&b0.x);
    const __half2* ha1 = reinterpret_cast<const __half2*>(&a1.x);
    const __half2* hb1 = reinterpret_cast<const __half2*>(&b1.x);

    __half2 acc = __float2half2_rn(0.0f);
#pragma unroll
    for (int i = 0; i < 4; i++) acc = __hfma2(ha0[i], hb0[i], acc);
#pragma unroll
    for (int i = 0; i < 4; i++) acc = __hfma2(ha1[i], hb1[i], acc);

    float2 f = __half22float2(acc);
    return f.x + f.y;
}

// ---------------------------------------------------------------------------
// Pass 2: 8 lanes per edge, 2 edges per lane-group -> 8 edges per warp.
// HFMA2 inner product; __launch_bounds__(256,8) caps regs at 32 so 8 blocks
// co-reside per SM (64 warps) — trade per-thread MLP for warp supply.
// ---------------------------------------------------------------------------
__global__ void __launch_bounds__(256, 8)
edge_dot(const int* __restrict__ esrc,
         const int* __restrict__ edst,
         float* __restrict__ out,
         int n_edges) {
    int warp = (blockIdx.x * blockDim.x + threadIdx.x) >> 5;
    int lane = threadIdx.x & 31;
    int grp  = lane >> 3;      // 0..3
    int gl   = lane & 7;       // 0..7

    int e0 = warp * 8 + grp;
    int e1 = e0 + 4;
    bool v0 = (e0 < n_edges);
    bool v1 = (e1 < n_edges);
    int c0 = v0 ? e0 : 0;
    int c1 = v1 ? e1 : 0;

    int si0 = esrc[c0], di0 = edst[c0];
    int si1 = esrc[c1], di1 = edst[c1];

    const uint4* A0 = reinterpret_cast<const uint4*>(g_eh) + (size_t)si0 * (H / 8);
    const uint4* B0 = reinterpret_cast<const uint4*>(g_eh) + (size_t)di0 * (H / 8);
    const uint4* A1 = reinterpret_cast<const uint4*>(g_eh) + (size_t)si1 * (H / 8);
    const uint4* B1 = reinterpret_cast<const uint4*>(g_eh) + (size_t)di1 * (H / 8);

    // Edge 0 gathers first, edge 1 second: lets ptxas overlap e1 loads with
    // e0 math while staying inside the 32-register budget.
    uint4 a00 = A0[gl], a01 = A0[gl + 8];
    uint4 b00 = B0[gl], b01 = B0[gl + 8];
    uint4 a10 = A1[gl], a11 = A1[gl + 8];
    uint4 b10 = B1[gl], b11 = B1[gl + 8];

    float acc0 = dot16h(a00, a01, b00, b01);
    float acc1 = dot16h(a10, a11, b10, b11);

    // Reduce across the 8-lane group (shfls serve all 4 groups at once).
    acc0 += __shfl_xor_sync(0xffffffffu, acc0, 4);
    acc0 += __shfl_xor_sync(0xffffffffu, acc0, 2);
    acc0 += __shfl_xor_sync(0xffffffffu, acc0, 1);
    acc1 += __shfl_xor_sync(0xffffffffu, acc1, 4);
    acc1 += __shfl_xor_sync(0xffffffffu, acc1, 2);
    acc1 += __shfl_xor_sync(0xffffffffu, acc1, 1);

    if (gl == 0) {
        if (v0) out[e0] = acc0;
        if (v1) out[e1] = acc1;
    }
}

// ---------------------------------------------------------------------------
// Launch
// ---------------------------------------------------------------------------
extern "C" void kernel_launch(void* const* d_in, const int* in_sizes, int n_in,
                              void* d_out, int out_size) {
    const float* emb = (const float*)d_in[0];
    const int* esrc = (const int*)d_in[1];
    const int* edst = (const int*)d_in[2];
    const float* d = (const float*)d_in[3];
    const float* scale = (const float*)d_in[4];
    float* out = (float*)d_out;

    int n_nodes = in_sizes[0] / H;
    int n_edges = in_sizes[1];

    const int threads = 256;                      // 8 warps/block
    int blocks1 = (n_nodes + 7) / 8;              // 1 row/warp
    normalize_rows<<<blocks1, threads>>>(emb, d, scale, n_nodes);

    int warps_needed = (n_edges + 7) / 8;         // 8 edges/warp
    int blocks2 = (warps_needed + 7) / 8;
    edge_dot<<<blocks2, threads>>>(esrc, edst, out, n_edges);
}

// round 10
// speedup vs baseline: 1.1992x; 1.1992x over previous
#include <cuda_runtime.h>
#include <cuda_fp16.h>
#include <cstdint>

// Problem constants (local_emb_D: N_NODES=100000, N_HIDDEN=128, N_EDGES=625000)
#define H 128
#define MAX_NODES 100000

// Single fp16 gather table (25.6 MB, fully L2-resident):
//   g[n][h] = normalize(emb)[n][h] * sqrt(d[h]*scale)
__device__ __half g_eh[(size_t)MAX_NODES * H];

// ---------------------------------------------------------------------------
// Pass 1: L2-normalize rows, fold sqrt(d*scale), store fp16.
// 8-lane group per row, 4 rows per warp. Each lane loads 4 float4 upfront
// (MLP_p1=4) -> better HBM latency hiding than the 1-load/warp variant.
// ---------------------------------------------------------------------------
__global__ void normalize_rows(const float* __restrict__ emb,
                               const float* __restrict__ d,
                               const float* __restrict__ scale,
                               int n_nodes) {
    int warp = (blockIdx.x * blockDim.x + threadIdx.x) >> 5;
    int lane = threadIdx.x & 31;
    int grp  = lane >> 3;          // 0..3 : row within warp's group of 4
    int gl   = lane & 7;           // 0..7 : lane within row group

    int row = warp * 4 + grp;
    if (row >= n_nodes) return;

    const float4* R = reinterpret_cast<const float4*>(emb) + (size_t)row * (H / 4);

    // 4 independent loads, issued before any math (MLP=4).
    float4 v0 = R[gl];
    float4 v1 = R[gl + 8];
    float4 v2 = R[gl + 16];
    float4 v3 = R[gl + 24];

    float s = v0.x * v0.x + v0.y * v0.y + v0.z * v0.z + v0.w * v0.w;
    s += v1.x * v1.x + v1.y * v1.y + v1.z * v1.z + v1.w * v1.w;
    s += v2.x * v2.x + v2.y * v2.y + v2.z * v2.z + v2.w * v2.w;
    s += v3.x * v3.x + v3.y * v3.y + v3.z * v3.z + v3.w * v3.w;

    // Reduce across the 8-lane group (3 shfls serve all 4 rows of the warp).
    s += __shfl_xor_sync(0xffffffffu, s, 4);
    s += __shfl_xor_sync(0xffffffffu, s, 2);
    s += __shfl_xor_sync(0xffffffffu, s, 1);

    float inv = 1.0f / fmaxf(sqrtf(s), 1e-12f);

    const float4* D = reinterpret_cast<const float4*>(d);
    float sc = scale[0];
    uint2* G = reinterpret_cast<uint2*>(g_eh) + (size_t)row * (H / 4);

#pragma unroll
    for (int j = 0; j < 4; j++) {
        float4 v = (j == 0) ? v0 : (j == 1) ? v1 : (j == 2) ? v2 : v3;
        int k = gl + j * 8;
        float4 dv = D[k];                       // d is tiny -> L1-resident
        float wx = sqrtf(dv.x * sc), wy = sqrtf(dv.y * sc);
        float wz = sqrtf(dv.z * sc), ww = sqrtf(dv.w * sc);
        __half2 h0 = __floats2half2_rn(v.x * inv * wx, v.y * inv * wy);
        __half2 h1 = __floats2half2_rn(v.z * inv * wz, v.w * inv * ww);
        uint2 p;
        p.x = *reinterpret_cast<unsigned int*>(&h0);
        p.y = *reinterpret_cast<unsigned int*>(&h1);
        G[k] = p;
    }
}

// ---------------------------------------------------------------------------
// Lane-local dot of 16 fp16 pairs via HFMA2 (8 fused ops), then one cvt.
// ---------------------------------------------------------------------------
__device__ __forceinline__ float dot16h(uint4 a0, uint4 a1, uint4 b0, uint4 b1) {
    const __half2* ha0 = reinterpret_cast<const __half2*>(&a0.x);
    const __half2* hb0 = reinterpret_cast<const __half2*>(&b0.x);
    const __half2* ha1 = reinterpret_cast<const __half2*>(&a1.x);
    const __half2* hb1 = reinterpret_cast<const __half2*>(&b1.x);

    __half2 acc = __float2half2_rn(0.0f);
#pragma unroll
    for (int i = 0; i < 4; i++) acc = __hfma2(ha0[i], hb0[i], acc);
#pragma unroll
    for (int i = 0; i < 4; i++) acc = __hfma2(ha1[i], hb1[i], acc);

    float2 f = __half22float2(acc);
    return f.x + f.y;
}

// ---------------------------------------------------------------------------
// Pass 2 (R8 verbatim — measured fastest at 22.9us, sits on the LTS cap):
// 8 lanes per edge, 2 edges per lane-group -> 8 edges per warp, MLP=8,
// natural register allocation (~40 regs, no launch_bounds).
// ---------------------------------------------------------------------------
__global__ void edge_dot(const int* __restrict__ esrc,
                         const int* __restrict__ edst,
                         float* __restrict__ out,
                         int n_edges) {
    int warp = (blockIdx.x * blockDim.x + threadIdx.x) >> 5;
    int lane = threadIdx.x & 31;
    int grp  = lane >> 3;      // 0..3
    int gl   = lane & 7;       // 0..7

    int e0 = warp * 8 + grp;
    int e1 = e0 + 4;
    bool v0 = (e0 < n_edges);
    bool v1 = (e1 < n_edges);
    int c0 = v0 ? e0 : 0;
    int c1 = v1 ? e1 : 0;

    int si0 = esrc[c0], di0 = edst[c0];
    int si1 = esrc[c1], di1 = edst[c1];

    const uint4* A0 = reinterpret_cast<const uint4*>(g_eh) + (size_t)si0 * (H / 8);
    const uint4* B0 = reinterpret_cast<const uint4*>(g_eh) + (size_t)di0 * (H / 8);
    const uint4* A1 = reinterpret_cast<const uint4*>(g_eh) + (size_t)si1 * (H / 8);
    const uint4* B1 = reinterpret_cast<const uint4*>(g_eh) + (size_t)di1 * (H / 8);

    // Issue all 8 gathers up front (MLP=8).
    uint4 a00 = A0[gl], a01 = A0[gl + 8];
    uint4 b00 = B0[gl], b01 = B0[gl + 8];
    uint4 a10 = A1[gl], a11 = A1[gl + 8];
    uint4 b10 = B1[gl], b11 = B1[gl + 8];

    float acc0 = dot16h(a00, a01, b00, b01);
    float acc1 = dot16h(a10, a11, b10, b11);

    // Reduce across the 8-lane group (shfls serve all 4 groups at once).
    acc0 += __shfl_xor_sync(0xffffffffu, acc0, 4);
    acc0 += __shfl_xor_sync(0xffffffffu, acc0, 2);
    acc0 += __shfl_xor_sync(0xffffffffu, acc0, 1);
    acc1 += __shfl_xor_sync(0xffffffffu, acc1, 4);
    acc1 += __shfl_xor_sync(0xffffffffu, acc1, 2);
    acc1 += __shfl_xor_sync(0xffffffffu, acc1, 1);

    if (gl == 0) {
        if (v0) out[e0] = acc0;
        if (v1) out[e1] = acc1;
    }
}

// ---------------------------------------------------------------------------
// Launch
// ---------------------------------------------------------------------------
extern "C" void kernel_launch(void* const* d_in, const int* in_sizes, int n_in,
                              void* d_out, int out_size) {
    const float* emb = (const float*)d_in[0];
    const int* esrc = (const int*)d_in[1];
    const int* edst = (const int*)d_in[2];
    const float* d = (const float*)d_in[3];
    const float* scale = (const float*)d_in[4];
    float* out = (float*)d_out;

    int n_nodes = in_sizes[0] / H;
    int n_edges = in_sizes[1];

    const int threads = 256;                      // 8 warps/block
    int rows_per_block = 32;                      // 4 rows/warp * 8 warps
    int blocks1 = (n_nodes + rows_per_block - 1) / rows_per_block;
    normalize_rows<<<blocks1, threads>>>(emb, d, scale, n_nodes);

    int warps_needed = (n_edges + 7) / 8;         // 8 edges/warp
    int blocks2 = (warps_needed + 7) / 8;
    edge_dot<<<blocks2, threads>>>(esrc, edst, out, n_edges);
}